// round 14
// baseline (speedup 1.0000x reference)
#include <cuda_runtime.h>
#include <cuda_fp16.h>
#include <math.h>

#define HDIM 256
#define WDIM 256
#define WF   129
#define BSZ  4
#define CSZ  128
#define NBLK 8

// scratch spectrum buffer, layout [b, c, wf, h] as half2 (~67 MB)
__device__ __half2 g_buf[(size_t)BSZ * CSZ * WF * HDIM];

// ---------------- packed half2 complex helpers ----------------
__device__ __forceinline__ __half2 hswap(__half2 a){ return __lowhigh2highlow(a); }

template<bool INV>
__device__ __forceinline__ __half2 mul_i_h(__half2 a){
    const __half2 sp = __floats2half2_rn(INV ? -1.f : 1.f, INV ? 1.f : -1.f);
    return __hmul2(hswap(a), sp);
}

template<bool INV>
__device__ __forceinline__ void bf4h(__half2& x0, __half2& x1, __half2& x2, __half2& x3){
    __half2 t0 = __hadd2(x0, x2), t1 = __hsub2(x0, x2);
    __half2 t2 = __hadd2(x1, x3), t3 = __hsub2(x1, x3);
    __half2 s3 = hswap(t3);
    const __half2 sp = __floats2half2_rn(INV ? -1.f : 1.f, INV ? 1.f : -1.f);
    const __half2 sn = __floats2half2_rn(INV ? 1.f : -1.f, INV ? -1.f : 1.f);
    x0 = __hadd2(t0, t2);
    x2 = __hsub2(t0, t2);
    x1 = __hfma2(s3, sp, t1);
    x3 = __hfma2(s3, sn, t1);
}

__device__ __forceinline__ __half2 cmulh_c(__half2 v, float wr, float wi_s){
    __half2 wrr = __floats2half2_rn(wr, wr);
    __half2 wni = __floats2half2_rn(-wi_s, wi_s);
    return __hfma2(hswap(v), wni, __hmul2(v, wrr));
}

__device__ __forceinline__ __half2 cmulh_t(__half2 v, uint2 u){
    return __hfma2(hswap(v), *(__half2*)&u.y, __hmul2(v, *(__half2*)&u.x));
}

template<bool INV>
__device__ __forceinline__ void dft16h(__half2 v[16]){
    const float S = INV ? 1.f : -1.f;
    bf4h<INV>(v[0], v[4], v[8],  v[12]);
    bf4h<INV>(v[1], v[5], v[9],  v[13]);
    bf4h<INV>(v[2], v[6], v[10], v[14]);
    bf4h<INV>(v[3], v[7], v[11], v[15]);
    v[5]  = cmulh_c(v[5],   0.92387953f, S*0.38268343f);
    v[9]  = cmulh_c(v[9],   0.70710678f, S*0.70710678f);
    v[13] = cmulh_c(v[13],  0.38268343f, S*0.92387953f);
    v[6]  = cmulh_c(v[6],   0.70710678f, S*0.70710678f);
    v[10] = mul_i_h<INV>(v[10]);
    v[14] = cmulh_c(v[14], -0.70710678f, S*0.70710678f);
    v[7]  = cmulh_c(v[7],   0.38268343f, S*0.92387953f);
    v[11] = cmulh_c(v[11], -0.70710678f, S*0.70710678f);
    v[15] = cmulh_c(v[15], -0.92387953f, -S*0.38268343f);
    bf4h<INV>(v[0],  v[1],  v[2],  v[3]);
    bf4h<INV>(v[4],  v[5],  v[6],  v[7]);
    bf4h<INV>(v[8],  v[9],  v[10], v[11]);
    bf4h<INV>(v[12], v[13], v[14], v[15]);
}

#define SLOT(k) ((((k) & 3) << 2) | ((k) >> 2))

__device__ __forceinline__ void build_twh(uint2* twf, uint2* twi, int tid){
    float s, c;
    __sincosf((float)tid * (-6.283185307179586f / 256.f), &s, &c);
    __half2 cc = __floats2half2_rn(c, c);
    __half2 nf = __floats2half2_rn(-s, s);
    __half2 ni = __floats2half2_rn(s, -s);
    uint2 u;
    u.x = *(unsigned int*)&cc;
    if (twf){ u.y = *(unsigned int*)&nf; twf[tid] = u; }
    if (twi){ u.y = *(unsigned int*)&ni; twi[tid] = u; }
}

// ---------------- MMA helpers ----------------
__device__ __forceinline__ unsigned s2u(const void* p){
    return (unsigned)__cvta_generic_to_shared(p);
}
__device__ __forceinline__ void ldmx4(unsigned* r, unsigned a){
    asm volatile("ldmatrix.sync.aligned.m8n8.x4.shared.b16 {%0,%1,%2,%3}, [%4];"
        : "=r"(r[0]), "=r"(r[1]), "=r"(r[2]), "=r"(r[3]) : "r"(a));
}
__device__ __forceinline__ void ldmx2t(unsigned& b0, unsigned& b1, unsigned a){
    asm volatile("ldmatrix.sync.aligned.m8n8.x2.trans.shared.b16 {%0,%1}, [%2];"
        : "=r"(b0), "=r"(b1) : "r"(a));
}
__device__ __forceinline__ void stmx2(unsigned a, unsigned r0, unsigned r1){
    asm volatile("stmatrix.sync.aligned.m8n8.x2.shared.b16 [%0], {%1,%2};"
        :: "r"(a), "r"(r0), "r"(r1) : "memory");
}
__device__ __forceinline__ void mma16816(float* c, const unsigned* a,
                                         unsigned b0, unsigned b1){
    asm volatile(
        "mma.sync.aligned.m16n8k16.row.col.f32.f16.f16.f32 "
        "{%0,%1,%2,%3}, {%4,%5,%6,%7}, {%8,%9}, {%0,%1,%2,%3};"
        : "+f"(c[0]), "+f"(c[1]), "+f"(c[2]), "+f"(c[3])
        : "r"(a[0]), "r"(a[1]), "r"(a[2]), "r"(a[3]), "r"(b0), "r"(b1));
}
__device__ __forceinline__ unsigned packh2(float a, float b){
    __half2 h = __floats2half2_rn(a, b);
    return *(unsigned*)&h;
}

// ---------------------------------------------------------------------------
// K1: row rfft, fp16 FFT. CTA = 32 rows, 2 real rows packed per complex FFT.
// Epilogue parity branch hoisted (r = e & 31 is thread-invariant).
// ---------------------------------------------------------------------------
__global__ void __launch_bounds__(256) k_rowfft(const float* __restrict__ x){
    extern __shared__ char smraw[];
    __half2* bufh = (__half2*)smraw;               // 4352 h2  [0, 17408)
    uint2*   twf  = (uint2*)(smraw + 17408);       // 256 u2

    const int tid = threadIdx.x;
    const int f = tid >> 4, t = tid & 15;
    const int bc = blockIdx.x >> 3;
    const int h0 = (blockIdx.x & 7) << 5;

    build_twh(twf, nullptr, tid);

    const float* r0 = x + ((size_t)bc * HDIM + h0 + 2 * f) * WDIM;
    __half2 v[16];
#pragma unroll
    for (int n1 = 0; n1 < 16; n1++)
        v[n1] = __floats2half2_rn(r0[16 * n1 + t], r0[WDIM + 16 * n1 + t]);
    dft16h<false>(v);
    __syncthreads();                               // twf ready

#pragma unroll
    for (int k1 = 0; k1 < 16; k1++){
        __half2 bv = v[SLOT(k1)];
        if (k1) bv = cmulh_t(bv, twf[t * k1]);
        bufh[f * 272 + k1 * 17 + t] = bv;
    }
    __syncwarp();                                  // half-warp exchange only
#pragma unroll
    for (int n2 = 0; n2 < 16; n2++)
        v[n2] = bufh[f * 272 + t * 17 + n2];
    __syncthreads();                               // T dead -> S (cross-group)
    dft16h<false>(v);
#pragma unroll
    for (int k2 = 0; k2 < 16; k2++)
        bufh[f * 257 + t + 16 * k2] = v[SLOT(k2)];
    __syncthreads();

    __half2* dst = g_buf + (size_t)bc * WF * HDIM;
    if ((tid & 1) == 0){
        for (int e = tid; e < WF * 32; e += 256){
            const int wf = e >> 5, r = e & 31, fp = r >> 1;
            float2 Z1 = __half22float2(bufh[fp * 257 + wf]);
            float2 Z2 = __half22float2(bufh[fp * 257 + ((256 - wf) & 255)]);
            dst[(size_t)wf * HDIM + h0 + r] = __floats2half2_rn(
                (Z1.x + Z2.x) * (1.f / 512.f), (Z1.y - Z2.y) * (1.f / 512.f));
        }
    } else {
        for (int e = tid; e < WF * 32; e += 256){
            const int wf = e >> 5, r = e & 31, fp = r >> 1;
            float2 Z1 = __half22float2(bufh[fp * 257 + wf]);
            float2 Z2 = __half22float2(bufh[fp * 257 + ((256 - wf) & 255)]);
            dst[(size_t)wf * HDIM + h0 + r] = __floats2half2_rn(
                (Z1.y + Z2.y) * (1.f / 512.f), (Z2.x - Z1.x) * (1.f / 512.f));
        }
    }
}

// ---------------------------------------------------------------------------
// K2: packed-fp16 column FFT + HMMA block MLP + inverse FFT, in-place g_buf.
// TWO bins per CTA: setup (twiddles/weights/biases) amortized over 2 bins.
// ---------------------------------------------------------------------------
__global__ void __launch_bounds__(256, 4) k_colfft_mlp(
        const float* __restrict__ w1g, const float* __restrict__ b1g,
        const float* __restrict__ w2g, const float* __restrict__ b2g){
    extern __shared__ char smraw[];
    __half*  Xs   = (__half*)smraw;                // 32 x 264   [0, 16896)
    __half2* Ts   = (__half2*)(smraw + 16896);     // transpose/Hs [16896, 34304)
    uint2*   twf  = (uint2*)(smraw + 34304);       // [34304, 36352)
    uint2*   twi  = (uint2*)(smraw + 36352);       // [36352, 38400)
    __half*  W1s  = (__half*)(smraw + 38400);      // 32 x 40    [38400, 40960)
    __half*  W2s  = (__half*)(smraw + 40960);      // 32 x 40    [40960, 43520)
    float*   b1s  = (float*)(smraw + 43520);       // 32         [43520, 43648)
    float*   b2s  = (float*)(smraw + 43648);       // 32         [43648, 43776)

    const int tid = threadIdx.x;
    const int f = tid >> 4, t = tid & 15;
    const int lane = tid & 31, wrp = tid >> 5;
    const int g = lane >> 2, tg = lane & 3;
    const int wfp = blockIdx.x % 65;
    const int bk = blockIdx.x / 65;
    const int k = bk & 7, b = bk >> 3;
    const int wf0 = wfp * 2;

    build_twh(twf, twi, tid);
    {   // W_stack = [[Wr, -Wi],[Wi, Wr]]; w1/w2 are [2][8][16 in][16 out]
        const int i = tid >> 4, o = tid & 15;
        float wr = w1g[k * 256 + i * 16 + o], wi = w1g[2048 + k * 256 + i * 16 + o];
        W1s[o * 40 + i]             = __float2half(wr);
        W1s[o * 40 + 16 + i]        = __float2half(-wi);
        W1s[(16 + o) * 40 + i]      = __float2half(wi);
        W1s[(16 + o) * 40 + 16 + i] = __float2half(wr);
        wr = w2g[k * 256 + i * 16 + o]; wi = w2g[2048 + k * 256 + i * 16 + o];
        W2s[o * 40 + i]             = __float2half(wr);
        W2s[o * 40 + 16 + i]        = __float2half(-wi);
        W2s[(16 + o) * 40 + i]      = __float2half(wi);
        W2s[(16 + o) * 40 + 16 + i] = __float2half(wr);
    }
    if (tid < 16){
        b1s[tid] = b1g[k * 16 + tid];  b1s[16 + tid] = b1g[128 + k * 16 + tid];
        b2s[tid] = b2g[k * 16 + tid];  b2s[16 + tid] = b2g[128 + k * 16 + tid];
    }

    for (int it = 0; it < 2; it++){
        const int wf = wf0 + it;
        if (wf >= WF) break;                       // uniform across CTA

        __half2* chp = g_buf + ((size_t)(b * CSZ + k * 16 + f) * WF + wf) * HDIM;

        // ---- forward column FFT ----
        __half2 v[16];
#pragma unroll
        for (int n1 = 0; n1 < 16; n1++) v[n1] = chp[16 * n1 + t];
        dft16h<false>(v);
        __syncthreads();             // it0: tables ready; it1: Ts/Xs reuse fence
#pragma unroll
        for (int k1 = 0; k1 < 16; k1++){
            __half2 bv = v[SLOT(k1)];
            if (k1) bv = cmulh_t(bv, twf[t * k1]);
            Ts[f * 272 + k1 * 17 + t] = bv;        // T write
        }
        __syncwarp();                              // half-warp exchange
#pragma unroll
        for (int n2 = 0; n2 < 16; n2++) v[n2] = Ts[f * 272 + t * 17 + n2];
        dft16h<false>(v);
#pragma unroll
        for (int k2 = 0; k2 < 16; k2++){           // X stacked-row write
            const int bin = t + (k2 << 4);
            __half2 z = v[SLOT(k2)];
            Xs[f * 264 + bin]        = __low2half(z);
            Xs[(16 + f) * 264 + bin] = __high2half(z);
        }
        __syncthreads();                           // X ready; Ts free -> Hs

        // ---- MLP via HMMA: each warp owns 32 columns ----
        {
            const unsigned rowsel = lane & 15;
            const unsigned XsB = s2u(Xs), HsB = s2u((__half*)Ts);
            float b1v0 = b1s[g], b1v1 = b1s[g + 8];
            float b1v2 = b1s[16 + g], b1v3 = b1s[24 + g];

            unsigned A1[4][4];
#pragma unroll
            for (int m = 0; m < 2; m++)
#pragma unroll
                for (int kt = 0; kt < 2; kt++)
                    ldmx4(A1[m * 2 + kt],
                          s2u(W1s) + (((m * 16 + rowsel) * 40 + kt * 16 + (lane >> 4) * 8) << 1));

#pragma unroll
            for (int nt = 0; nt < 4; nt++){
                const int n0 = wrp * 32 + nt * 8;
                unsigned bx0, bx1, by0, by1;
                ldmx2t(bx0, bx1, XsB + ((rowsel * 264 + n0) << 1));
                ldmx2t(by0, by1, XsB + (((16 + rowsel) * 264 + n0) << 1));
                float cr[4] = {0.f, 0.f, 0.f, 0.f}, ci[4] = {0.f, 0.f, 0.f, 0.f};
                mma16816(cr, A1[0], bx0, bx1);
                mma16816(cr, A1[1], by0, by1);
                mma16816(ci, A1[2], bx0, bx1);
                mma16816(ci, A1[3], by0, by1);
                unsigned hr0 = packh2(fmaxf(cr[0] + b1v0, 0.f), fmaxf(cr[1] + b1v0, 0.f));
                unsigned hr1 = packh2(fmaxf(cr[2] + b1v1, 0.f), fmaxf(cr[3] + b1v1, 0.f));
                unsigned hi0 = packh2(fmaxf(ci[0] + b1v2, 0.f), fmaxf(ci[1] + b1v2, 0.f));
                unsigned hi1 = packh2(fmaxf(ci[2] + b1v3, 0.f), fmaxf(ci[3] + b1v3, 0.f));
                stmx2(HsB + ((rowsel * 264 + n0) << 1), hr0, hr1);
                stmx2(HsB + (((16 + rowsel) * 264 + n0) << 1), hi0, hi1);
            }
            __syncwarp();

            unsigned A2[4][4];
#pragma unroll
            for (int m = 0; m < 2; m++)
#pragma unroll
                for (int kt = 0; kt < 2; kt++)
                    ldmx4(A2[m * 2 + kt],
                          s2u(W2s) + (((m * 16 + rowsel) * 40 + kt * 16 + (lane >> 4) * 8) << 1));
            float b2v0 = b2s[g], b2v1 = b2s[g + 8];
            float b2v2 = b2s[16 + g], b2v3 = b2s[24 + g];

#pragma unroll
            for (int nt = 0; nt < 4; nt++){
                const int n0 = wrp * 32 + nt * 8;
                unsigned bx0, bx1, by0, by1;
                ldmx2t(bx0, bx1, HsB + ((rowsel * 264 + n0) << 1));
                ldmx2t(by0, by1, HsB + (((16 + rowsel) * 264 + n0) << 1));
                float cr[4] = {0.f, 0.f, 0.f, 0.f}, ci[4] = {0.f, 0.f, 0.f, 0.f};
                mma16816(cr, A2[0], bx0, bx1);
                mma16816(cr, A2[1], by0, by1);
                mma16816(ci, A2[2], bx0, bx1);
                mma16816(ci, A2[3], by0, by1);
#pragma unroll
                for (int j = 0; j < 4; j++){
                    const int o = g + ((j >> 1) << 3);
                    const int bin = n0 + 2 * tg + (j & 1);
                    const float yr = cr[j] + ((j >> 1) ? b2v1 : b2v0);
                    const float yi = ci[j] + ((j >> 1) ? b2v3 : b2v2);
                    const float sr = copysignf(fmaxf(fabsf(yr) - 0.01f, 0.f), yr);
                    const float si = copysignf(fmaxf(fabsf(yi) - 0.01f, 0.f), yi);
                    const float xr = __half2float(Xs[o * 264 + bin]);
                    const float xi = __half2float(Xs[(o + 16) * 264 + bin]);
                    Xs[o * 264 + bin]        = __float2half(sr * xr - si * xi);
                    Xs[(o + 16) * 264 + bin] = __float2half(sr * xi + si * xr);
                }
            }
        }
        __syncthreads();                           // result in Xs; Hs reads done

        // ---- inverse column FFT (A from Xs stacked rows, transpose via Ts) ----
#pragma unroll
        for (int k2 = 0; k2 < 16; k2++){
            const int bin = t + (k2 << 4);
            v[k2] = __halves2half2(Xs[f * 264 + bin], Xs[(16 + f) * 264 + bin]);
        }
        dft16h<true>(v);
#pragma unroll
        for (int m2 = 0; m2 < 16; m2++){
            __half2 q = v[SLOT(m2)];
            if (m2) q = cmulh_t(q, twi[m2 * t]);
            Ts[f * 272 + m2 * 17 + t] = q;         // T write
        }
        __syncwarp();
#pragma unroll
        for (int n = 0; n < 16; n++) v[n] = Ts[f * 272 + t * 17 + n];   // T read
        dft16h<true>(v);
#pragma unroll
        for (int m1 = 0; m1 < 16; m1++)
            chp[16 * m1 + t] = v[SLOT(m1)];
    }
}

// ---------------------------------------------------------------------------
// K3: row irfft, fp16 FFT. Hermitian extension + edge-bin imag zeroing ==
// irfft semantics. Scale 1/256 + residual in fp32.
// ---------------------------------------------------------------------------
__global__ void __launch_bounds__(256) k_rowifft(const float* __restrict__ x,
                                                 float* __restrict__ out){
    extern __shared__ char smraw[];
    __half2* bufh = (__half2*)smraw;               // 4352 h2
    uint2*   twi  = (uint2*)(smraw + 17408);       // 256 u2

    const int tid = threadIdx.x;
    const int f = tid >> 4, t = tid & 15;
    const int bc = blockIdx.x >> 3;
    const int h0 = (blockIdx.x & 7) << 5;

    build_twh(nullptr, twi, tid);

    const __half2* gsrc = g_buf + (size_t)bc * WF * HDIM;
    for (int e = tid; e < WF * 16; e += 256){
        const int wf = e >> 4, fp = e & 15;
        uint2 u = *(const uint2*)(gsrc + (size_t)wf * HDIM + h0 + 2 * fp);
        float2 a  = __half22float2(*(__half2*)&u.x);
        float2 bq = __half22float2(*(__half2*)&u.y);
        float ay = a.y, by = bq.y;
        if (wf == 0 || wf == 128){ ay = 0.f; by = 0.f; }
        bufh[fp * 257 + wf] = __floats2half2_rn(a.x - by, ay + bq.x);
        if (wf >= 1 && wf <= 127)
            bufh[fp * 257 + 256 - wf] = __floats2half2_rn(a.x + by, bq.x - ay);
    }
    __syncthreads();

    __half2 v[16];
#pragma unroll
    for (int k2 = 0; k2 < 16; k2++) v[k2] = bufh[f * 257 + t + 16 * k2];
    __syncthreads();                               // S dead -> T (cross-group)
    dft16h<true>(v);
#pragma unroll
    for (int m2 = 0; m2 < 16; m2++){
        __half2 q = v[SLOT(m2)];
        if (m2) q = cmulh_t(q, twi[m2 * t]);
        bufh[f * 272 + m2 * 17 + t] = q;
    }
    __syncwarp();                                  // half-warp exchange only
#pragma unroll
    for (int n = 0; n < 16; n++) v[n] = bufh[f * 272 + t * 17 + n];
    dft16h<true>(v);

    const float* bias0 = x   + ((size_t)bc * HDIM + h0 + 2 * f) * WDIM;
    float*       o0    = out + ((size_t)bc * HDIM + h0 + 2 * f) * WDIM;
#pragma unroll
    for (int m1 = 0; m1 < 16; m1++){
        float2 z = __half22float2(v[SLOT(m1)]);
        const int w_ = 16 * m1 + t;
        o0[w_]        = z.x * (1.f / 256.f) + bias0[w_];
        o0[WDIM + w_] = z.y * (1.f / 256.f) + bias0[WDIM + w_];
    }
}

extern "C" void kernel_launch(void* const* d_in, const int* in_sizes, int n_in,
                              void* d_out, int out_size) {
    const float* x  = (const float*)d_in[0];
    const float* w1 = (const float*)d_in[1];
    const float* b1 = (const float*)d_in[2];
    const float* w2 = (const float*)d_in[3];
    const float* b2 = (const float*)d_in[4];
    float* out = (float*)d_out;

    const int SMEM_ROW = 19456;
    const int SMEM_COL = 43776;

    cudaFuncSetAttribute(k_rowfft,     cudaFuncAttributeMaxDynamicSharedMemorySize, SMEM_ROW);
    cudaFuncSetAttribute(k_colfft_mlp, cudaFuncAttributeMaxDynamicSharedMemorySize, SMEM_COL);
    cudaFuncSetAttribute(k_rowifft,    cudaFuncAttributeMaxDynamicSharedMemorySize, SMEM_ROW);

    k_rowfft<<<BSZ * CSZ * (HDIM / 32), 256, SMEM_ROW>>>(x);
    k_colfft_mlp<<<BSZ * NBLK * 65, 256, SMEM_COL>>>(w1, b1, w2, b2);
    k_rowifft<<<BSZ * CSZ * (HDIM / 32), 256, SMEM_ROW>>>(x, out);
}

// round 15
// speedup vs baseline: 1.0437x; 1.0437x over previous
#include <cuda_runtime.h>
#include <cuda_fp16.h>
#include <math.h>

#define HDIM 256
#define WDIM 256
#define WF   129
#define BSZ  4
#define CSZ  128
#define NBLK 8

// scratch spectrum buffer, layout [b, c, wf, h] as half2 (~67 MB)
__device__ __half2 g_buf[(size_t)BSZ * CSZ * WF * HDIM];

// ---------------- packed half2 complex helpers ----------------
__device__ __forceinline__ __half2 hswap(__half2 a){ return __lowhigh2highlow(a); }

template<bool INV>
__device__ __forceinline__ __half2 mul_i_h(__half2 a){
    const __half2 sp = __floats2half2_rn(INV ? -1.f : 1.f, INV ? 1.f : -1.f);
    return __hmul2(hswap(a), sp);
}

template<bool INV>
__device__ __forceinline__ void bf4h(__half2& x0, __half2& x1, __half2& x2, __half2& x3){
    __half2 t0 = __hadd2(x0, x2), t1 = __hsub2(x0, x2);
    __half2 t2 = __hadd2(x1, x3), t3 = __hsub2(x1, x3);
    __half2 s3 = hswap(t3);
    const __half2 sp = __floats2half2_rn(INV ? -1.f : 1.f, INV ? 1.f : -1.f);
    const __half2 sn = __floats2half2_rn(INV ? 1.f : -1.f, INV ? -1.f : 1.f);
    x0 = __hadd2(t0, t2);
    x2 = __hsub2(t0, t2);
    x1 = __hfma2(s3, sp, t1);
    x3 = __hfma2(s3, sn, t1);
}

__device__ __forceinline__ __half2 cmulh_c(__half2 v, float wr, float wi_s){
    __half2 wrr = __floats2half2_rn(wr, wr);
    __half2 wni = __floats2half2_rn(-wi_s, wi_s);
    return __hfma2(hswap(v), wni, __hmul2(v, wrr));
}

__device__ __forceinline__ __half2 cmulh_t(__half2 v, uint2 u){
    return __hfma2(hswap(v), *(__half2*)&u.y, __hmul2(v, *(__half2*)&u.x));
}

template<bool INV>
__device__ __forceinline__ void dft16h(__half2 v[16]){
    const float S = INV ? 1.f : -1.f;
    bf4h<INV>(v[0], v[4], v[8],  v[12]);
    bf4h<INV>(v[1], v[5], v[9],  v[13]);
    bf4h<INV>(v[2], v[6], v[10], v[14]);
    bf4h<INV>(v[3], v[7], v[11], v[15]);
    v[5]  = cmulh_c(v[5],   0.92387953f, S*0.38268343f);
    v[9]  = cmulh_c(v[9],   0.70710678f, S*0.70710678f);
    v[13] = cmulh_c(v[13],  0.38268343f, S*0.92387953f);
    v[6]  = cmulh_c(v[6],   0.70710678f, S*0.70710678f);
    v[10] = mul_i_h<INV>(v[10]);
    v[14] = cmulh_c(v[14], -0.70710678f, S*0.70710678f);
    v[7]  = cmulh_c(v[7],   0.38268343f, S*0.92387953f);
    v[11] = cmulh_c(v[11], -0.70710678f, S*0.70710678f);
    v[15] = cmulh_c(v[15], -0.92387953f, -S*0.38268343f);
    bf4h<INV>(v[0],  v[1],  v[2],  v[3]);
    bf4h<INV>(v[4],  v[5],  v[6],  v[7]);
    bf4h<INV>(v[8],  v[9],  v[10], v[11]);
    bf4h<INV>(v[12], v[13], v[14], v[15]);
}

#define SLOT(k) ((((k) & 3) << 2) | ((k) >> 2))

__device__ __forceinline__ void build_twh(uint2* twf, uint2* twi, int tid){
    float s, c;
    __sincosf((float)tid * (-6.283185307179586f / 256.f), &s, &c);
    __half2 cc = __floats2half2_rn(c, c);
    __half2 nf = __floats2half2_rn(-s, s);
    __half2 ni = __floats2half2_rn(s, -s);
    uint2 u;
    u.x = *(unsigned int*)&cc;
    if (twf){ u.y = *(unsigned int*)&nf; twf[tid] = u; }
    if (twi){ u.y = *(unsigned int*)&ni; twi[tid] = u; }
}

// ---------------- MMA helpers ----------------
__device__ __forceinline__ unsigned s2u(const void* p){
    return (unsigned)__cvta_generic_to_shared(p);
}
__device__ __forceinline__ void ldmx4(unsigned* r, unsigned a){
    asm volatile("ldmatrix.sync.aligned.m8n8.x4.shared.b16 {%0,%1,%2,%3}, [%4];"
        : "=r"(r[0]), "=r"(r[1]), "=r"(r[2]), "=r"(r[3]) : "r"(a));
}
__device__ __forceinline__ void ldmx2t(unsigned& b0, unsigned& b1, unsigned a){
    asm volatile("ldmatrix.sync.aligned.m8n8.x2.trans.shared.b16 {%0,%1}, [%2];"
        : "=r"(b0), "=r"(b1) : "r"(a));
}
__device__ __forceinline__ void stmx2(unsigned a, unsigned r0, unsigned r1){
    asm volatile("stmatrix.sync.aligned.m8n8.x2.shared.b16 [%0], {%1,%2};"
        :: "r"(a), "r"(r0), "r"(r1) : "memory");
}
__device__ __forceinline__ void mma16816(float* c, const unsigned* a,
                                         unsigned b0, unsigned b1){
    asm volatile(
        "mma.sync.aligned.m16n8k16.row.col.f32.f16.f16.f32 "
        "{%0,%1,%2,%3}, {%4,%5,%6,%7}, {%8,%9}, {%0,%1,%2,%3};"
        : "+f"(c[0]), "+f"(c[1]), "+f"(c[2]), "+f"(c[3])
        : "r"(a[0]), "r"(a[1]), "r"(a[2]), "r"(a[3]), "r"(b0), "r"(b1));
}
__device__ __forceinline__ unsigned packh2(float a, float b){
    __half2 h = __floats2half2_rn(a, b);
    return *(unsigned*)&h;
}

// ---------------------------------------------------------------------------
// K1: row rfft, fp16 FFT. CTA = 32 rows, 2 real rows packed per complex FFT.
// Pair-fused epilogue: one Z1/Z2 load pair -> both packed rows -> one STG.64.
// ---------------------------------------------------------------------------
__global__ void __launch_bounds__(256) k_rowfft(const float* __restrict__ x){
    extern __shared__ char smraw[];
    __half2* bufh = (__half2*)smraw;               // 4352 h2  [0, 17408)
    uint2*   twf  = (uint2*)(smraw + 17408);       // 256 u2

    const int tid = threadIdx.x;
    const int f = tid >> 4, t = tid & 15;
    const int bc = blockIdx.x >> 3;
    const int h0 = (blockIdx.x & 7) << 5;

    build_twh(twf, nullptr, tid);

    const float* r0 = x + ((size_t)bc * HDIM + h0 + 2 * f) * WDIM;
    __half2 v[16];
#pragma unroll
    for (int n1 = 0; n1 < 16; n1++)
        v[n1] = __floats2half2_rn(r0[16 * n1 + t], r0[WDIM + 16 * n1 + t]);
    dft16h<false>(v);
    __syncthreads();                               // twf ready

#pragma unroll
    for (int k1 = 0; k1 < 16; k1++){
        __half2 bv = v[SLOT(k1)];
        if (k1) bv = cmulh_t(bv, twf[t * k1]);
        bufh[f * 272 + k1 * 17 + t] = bv;
    }
    __syncwarp();                                  // half-warp exchange only
#pragma unroll
    for (int n2 = 0; n2 < 16; n2++)
        v[n2] = bufh[f * 272 + t * 17 + n2];
    __syncthreads();                               // T dead -> S (cross-group)
    dft16h<false>(v);
#pragma unroll
    for (int k2 = 0; k2 < 16; k2++)
        bufh[f * 257 + t + 16 * k2] = v[SLOT(k2)];
    __syncthreads();

    __half2* dst = g_buf + (size_t)bc * WF * HDIM;
    for (int e = tid; e < WF * 16; e += 256){
        const int wf = e >> 4, fp = e & 15;
        float2 Z1 = __half22float2(bufh[fp * 257 + wf]);
        float2 Z2 = __half22float2(bufh[fp * 257 + ((256 - wf) & 255)]);
        __half2 o0 = __floats2half2_rn((Z1.x + Z2.x) * (1.f / 512.f),
                                       (Z1.y - Z2.y) * (1.f / 512.f));
        __half2 o1 = __floats2half2_rn((Z1.y + Z2.y) * (1.f / 512.f),
                                       (Z2.x - Z1.x) * (1.f / 512.f));
        uint2 st;
        st.x = *(unsigned*)&o0;
        st.y = *(unsigned*)&o1;
        *(uint2*)(dst + (size_t)wf * HDIM + h0 + 2 * fp) = st;
    }
}

// ---------------------------------------------------------------------------
// K2: packed-fp16 column FFT + HMMA block MLP + inverse FFT, in-place g_buf.
// (round-13 validated version: one bin per CTA)
// ---------------------------------------------------------------------------
__global__ void __launch_bounds__(256, 4) k_colfft_mlp(
        const float* __restrict__ w1g, const float* __restrict__ b1g,
        const float* __restrict__ w2g, const float* __restrict__ b2g){
    extern __shared__ char smraw[];
    __half*  Xs   = (__half*)smraw;                // 32 x 264   [0, 16896)
    __half2* Ts   = (__half2*)(smraw + 16896);     // transpose/Hs [16896, 34304)
    uint2*   twf  = (uint2*)(smraw + 34304);       // [34304, 36352)
    uint2*   twi  = (uint2*)(smraw + 36352);       // [36352, 38400)
    __half*  W1s  = (__half*)(smraw + 38400);      // 32 x 40    [38400, 40960)
    __half*  W2s  = (__half*)(smraw + 40960);      // 32 x 40    [40960, 43520)
    float*   b1s  = (float*)(smraw + 43520);       // 32         [43520, 43648)
    float*   b2s  = (float*)(smraw + 43648);       // 32         [43648, 43776)

    const int tid = threadIdx.x;
    const int f = tid >> 4, t = tid & 15;
    const int lane = tid & 31, wrp = tid >> 5;
    const int g = lane >> 2, tg = lane & 3;
    const int wf = blockIdx.x % WF;
    const int bk = blockIdx.x / WF;
    const int k = bk & 7, b = bk >> 3;

    build_twh(twf, twi, tid);
    {   // W_stack = [[Wr, -Wi],[Wi, Wr]]; w1/w2 are [2][8][16 in][16 out]
        const int i = tid >> 4, o = tid & 15;
        float wr = w1g[k * 256 + i * 16 + o], wi = w1g[2048 + k * 256 + i * 16 + o];
        W1s[o * 40 + i]             = __float2half(wr);
        W1s[o * 40 + 16 + i]        = __float2half(-wi);
        W1s[(16 + o) * 40 + i]      = __float2half(wi);
        W1s[(16 + o) * 40 + 16 + i] = __float2half(wr);
        wr = w2g[k * 256 + i * 16 + o]; wi = w2g[2048 + k * 256 + i * 16 + o];
        W2s[o * 40 + i]             = __float2half(wr);
        W2s[o * 40 + 16 + i]        = __float2half(-wi);
        W2s[(16 + o) * 40 + i]      = __float2half(wi);
        W2s[(16 + o) * 40 + 16 + i] = __float2half(wr);
    }
    if (tid < 16){
        b1s[tid] = b1g[k * 16 + tid];  b1s[16 + tid] = b1g[128 + k * 16 + tid];
        b2s[tid] = b2g[k * 16 + tid];  b2s[16 + tid] = b2g[128 + k * 16 + tid];
    }

    __half2* chp = g_buf + ((size_t)(b * CSZ + k * 16 + f) * WF + wf) * HDIM;

    // ---- forward column FFT ----
    __half2 v[16];
#pragma unroll
    for (int n1 = 0; n1 < 16; n1++) v[n1] = chp[16 * n1 + t];
    dft16h<false>(v);
    __syncthreads();                               // tables + weights ready
#pragma unroll
    for (int k1 = 0; k1 < 16; k1++){
        __half2 bv = v[SLOT(k1)];
        if (k1) bv = cmulh_t(bv, twf[t * k1]);
        Ts[f * 272 + k1 * 17 + t] = bv;            // T write
    }
    __syncwarp();                                  // half-warp exchange
#pragma unroll
    for (int n2 = 0; n2 < 16; n2++) v[n2] = Ts[f * 272 + t * 17 + n2];  // T read
    dft16h<false>(v);
#pragma unroll
    for (int k2 = 0; k2 < 16; k2++){               // X stacked-row write
        const int bin = t + (k2 << 4);
        __half2 z = v[SLOT(k2)];
        Xs[f * 264 + bin]        = __low2half(z);
        Xs[(16 + f) * 264 + bin] = __high2half(z);
    }
    __syncthreads();                               // X ready; Ts free -> Hs

    // ---- MLP via HMMA: each warp owns 32 columns ----
    {
        const unsigned rowsel = lane & 15;
        const unsigned XsB = s2u(Xs), HsB = s2u((__half*)Ts);
        float b1v0 = b1s[g], b1v1 = b1s[g + 8], b1v2 = b1s[16 + g], b1v3 = b1s[24 + g];

        unsigned A1[4][4];
#pragma unroll
        for (int m = 0; m < 2; m++)
#pragma unroll
            for (int kt = 0; kt < 2; kt++)
                ldmx4(A1[m * 2 + kt],
                      s2u(W1s) + (((m * 16 + rowsel) * 40 + kt * 16 + (lane >> 4) * 8) << 1));

#pragma unroll
        for (int nt = 0; nt < 4; nt++){
            const int n0 = wrp * 32 + nt * 8;
            unsigned bx0, bx1, by0, by1;
            ldmx2t(bx0, bx1, XsB + ((rowsel * 264 + n0) << 1));
            ldmx2t(by0, by1, XsB + (((16 + rowsel) * 264 + n0) << 1));
            float cr[4] = {0.f, 0.f, 0.f, 0.f}, ci[4] = {0.f, 0.f, 0.f, 0.f};
            mma16816(cr, A1[0], bx0, bx1);
            mma16816(cr, A1[1], by0, by1);
            mma16816(ci, A1[2], bx0, bx1);
            mma16816(ci, A1[3], by0, by1);
            unsigned hr0 = packh2(fmaxf(cr[0] + b1v0, 0.f), fmaxf(cr[1] + b1v0, 0.f));
            unsigned hr1 = packh2(fmaxf(cr[2] + b1v1, 0.f), fmaxf(cr[3] + b1v1, 0.f));
            unsigned hi0 = packh2(fmaxf(ci[0] + b1v2, 0.f), fmaxf(ci[1] + b1v2, 0.f));
            unsigned hi1 = packh2(fmaxf(ci[2] + b1v3, 0.f), fmaxf(ci[3] + b1v3, 0.f));
            stmx2(HsB + ((rowsel * 264 + n0) << 1), hr0, hr1);
            stmx2(HsB + (((16 + rowsel) * 264 + n0) << 1), hi0, hi1);
        }
        __syncwarp();

        unsigned A2[4][4];
#pragma unroll
        for (int m = 0; m < 2; m++)
#pragma unroll
            for (int kt = 0; kt < 2; kt++)
                ldmx4(A2[m * 2 + kt],
                      s2u(W2s) + (((m * 16 + rowsel) * 40 + kt * 16 + (lane >> 4) * 8) << 1));
        float b2v0 = b2s[g], b2v1 = b2s[g + 8], b2v2 = b2s[16 + g], b2v3 = b2s[24 + g];

#pragma unroll
        for (int nt = 0; nt < 4; nt++){
            const int n0 = wrp * 32 + nt * 8;
            unsigned bx0, bx1, by0, by1;
            ldmx2t(bx0, bx1, HsB + ((rowsel * 264 + n0) << 1));
            ldmx2t(by0, by1, HsB + (((16 + rowsel) * 264 + n0) << 1));
            float cr[4] = {0.f, 0.f, 0.f, 0.f}, ci[4] = {0.f, 0.f, 0.f, 0.f};
            mma16816(cr, A2[0], bx0, bx1);
            mma16816(cr, A2[1], by0, by1);
            mma16816(ci, A2[2], bx0, bx1);
            mma16816(ci, A2[3], by0, by1);
#pragma unroll
            for (int j = 0; j < 4; j++){
                const int o = g + ((j >> 1) << 3);
                const int bin = n0 + 2 * tg + (j & 1);
                const float yr = cr[j] + ((j >> 1) ? b2v1 : b2v0);
                const float yi = ci[j] + ((j >> 1) ? b2v3 : b2v2);
                const float sr = copysignf(fmaxf(fabsf(yr) - 0.01f, 0.f), yr);
                const float si = copysignf(fmaxf(fabsf(yi) - 0.01f, 0.f), yi);
                const float xr = __half2float(Xs[o * 264 + bin]);
                const float xi = __half2float(Xs[(o + 16) * 264 + bin]);
                Xs[o * 264 + bin]        = __float2half(sr * xr - si * xi);
                Xs[(o + 16) * 264 + bin] = __float2half(sr * xi + si * xr);
            }
        }
    }
    __syncthreads();                               // result in Xs; Hs reads done

    // ---- inverse column FFT (A from Xs stacked rows, transpose via Ts) ----
#pragma unroll
    for (int k2 = 0; k2 < 16; k2++){
        const int bin = t + (k2 << 4);
        v[k2] = __halves2half2(Xs[f * 264 + bin], Xs[(16 + f) * 264 + bin]);
    }
    dft16h<true>(v);
#pragma unroll
    for (int m2 = 0; m2 < 16; m2++){
        __half2 q = v[SLOT(m2)];
        if (m2) q = cmulh_t(q, twi[m2 * t]);
        Ts[f * 272 + m2 * 17 + t] = q;             // T write
    }
    __syncwarp();
#pragma unroll
    for (int n = 0; n < 16; n++) v[n] = Ts[f * 272 + t * 17 + n];       // T read
    dft16h<true>(v);
#pragma unroll
    for (int m1 = 0; m1 < 16; m1++)
        chp[16 * m1 + t] = v[SLOT(m1)];
}

// ---------------------------------------------------------------------------
// K3: row irfft, fp16 FFT. Hermitian extension + edge-bin imag zeroing ==
// irfft semantics. Scale 1/256 + residual in fp32.
// ---------------------------------------------------------------------------
__global__ void __launch_bounds__(256) k_rowifft(const float* __restrict__ x,
                                                 float* __restrict__ out){
    extern __shared__ char smraw[];
    __half2* bufh = (__half2*)smraw;               // 4352 h2
    uint2*   twi  = (uint2*)(smraw + 17408);       // 256 u2

    const int tid = threadIdx.x;
    const int f = tid >> 4, t = tid & 15;
    const int bc = blockIdx.x >> 3;
    const int h0 = (blockIdx.x & 7) << 5;

    build_twh(nullptr, twi, tid);

    const __half2* gsrc = g_buf + (size_t)bc * WF * HDIM;
    for (int e = tid; e < WF * 16; e += 256){
        const int wf = e >> 4, fp = e & 15;
        uint2 u = *(const uint2*)(gsrc + (size_t)wf * HDIM + h0 + 2 * fp);
        float2 a  = __half22float2(*(__half2*)&u.x);
        float2 bq = __half22float2(*(__half2*)&u.y);
        float ay = a.y, by = bq.y;
        if (wf == 0 || wf == 128){ ay = 0.f; by = 0.f; }
        bufh[fp * 257 + wf] = __floats2half2_rn(a.x - by, ay + bq.x);
        if (wf >= 1 && wf <= 127)
            bufh[fp * 257 + 256 - wf] = __floats2half2_rn(a.x + by, bq.x - ay);
    }
    __syncthreads();

    __half2 v[16];
#pragma unroll
    for (int k2 = 0; k2 < 16; k2++) v[k2] = bufh[f * 257 + t + 16 * k2];
    __syncthreads();                               // S dead -> T (cross-group)
    dft16h<true>(v);
#pragma unroll
    for (int m2 = 0; m2 < 16; m2++){
        __half2 q = v[SLOT(m2)];
        if (m2) q = cmulh_t(q, twi[m2 * t]);
        bufh[f * 272 + m2 * 17 + t] = q;
    }
    __syncwarp();                                  // half-warp exchange only
#pragma unroll
    for (int n = 0; n < 16; n++) v[n] = bufh[f * 272 + t * 17 + n];
    dft16h<true>(v);

    const float* bias0 = x   + ((size_t)bc * HDIM + h0 + 2 * f) * WDIM;
    float*       o0    = out + ((size_t)bc * HDIM + h0 + 2 * f) * WDIM;
#pragma unroll
    for (int m1 = 0; m1 < 16; m1++){
        float2 z = __half22float2(v[SLOT(m1)]);
        const int w_ = 16 * m1 + t;
        o0[w_]        = z.x * (1.f / 256.f) + bias0[w_];
        o0[WDIM + w_] = z.y * (1.f / 256.f) + bias0[WDIM + w_];
    }
}

extern "C" void kernel_launch(void* const* d_in, const int* in_sizes, int n_in,
                              void* d_out, int out_size) {
    const float* x  = (const float*)d_in[0];
    const float* w1 = (const float*)d_in[1];
    const float* b1 = (const float*)d_in[2];
    const float* w2 = (const float*)d_in[3];
    const float* b2 = (const float*)d_in[4];
    float* out = (float*)d_out;

    const int SMEM_ROW = 19456;
    const int SMEM_COL = 43776;

    cudaFuncSetAttribute(k_rowfft,     cudaFuncAttributeMaxDynamicSharedMemorySize, SMEM_ROW);
    cudaFuncSetAttribute(k_colfft_mlp, cudaFuncAttributeMaxDynamicSharedMemorySize, SMEM_COL);
    cudaFuncSetAttribute(k_rowifft,    cudaFuncAttributeMaxDynamicSharedMemorySize, SMEM_ROW);

    k_rowfft<<<BSZ * CSZ * (HDIM / 32), 256, SMEM_ROW>>>(x);
    k_colfft_mlp<<<BSZ * NBLK * WF, 256, SMEM_COL>>>(w1, b1, w2, b2);
    k_rowifft<<<BSZ * CSZ * (HDIM / 32), 256, SMEM_ROW>>>(x, out);
}

// round 16
// speedup vs baseline: 1.0451x; 1.0013x over previous
#include <cuda_runtime.h>
#include <cuda_fp16.h>
#include <math.h>

#define HDIM 256
#define WDIM 256
#define WF   129
#define BSZ  4
#define CSZ  128
#define NBLK 8

// scratch spectrum buffer, layout [b, c, wf, h] as half2 (~67 MB)
__device__ __half2 g_buf[(size_t)BSZ * CSZ * WF * HDIM];

// ---------------- packed half2 complex helpers ----------------
__device__ __forceinline__ __half2 hswap(__half2 a){ return __lowhigh2highlow(a); }

template<bool INV>
__device__ __forceinline__ __half2 mul_i_h(__half2 a){
    const __half2 sp = __floats2half2_rn(INV ? -1.f : 1.f, INV ? 1.f : -1.f);
    return __hmul2(hswap(a), sp);
}

template<bool INV>
__device__ __forceinline__ void bf4h(__half2& x0, __half2& x1, __half2& x2, __half2& x3){
    __half2 t0 = __hadd2(x0, x2), t1 = __hsub2(x0, x2);
    __half2 t2 = __hadd2(x1, x3), t3 = __hsub2(x1, x3);
    __half2 s3 = hswap(t3);
    const __half2 sp = __floats2half2_rn(INV ? -1.f : 1.f, INV ? 1.f : -1.f);
    const __half2 sn = __floats2half2_rn(INV ? 1.f : -1.f, INV ? -1.f : 1.f);
    x0 = __hadd2(t0, t2);
    x2 = __hsub2(t0, t2);
    x1 = __hfma2(s3, sp, t1);
    x3 = __hfma2(s3, sn, t1);
}

__device__ __forceinline__ __half2 cmulh_c(__half2 v, float wr, float wi_s){
    __half2 wrr = __floats2half2_rn(wr, wr);
    __half2 wni = __floats2half2_rn(-wi_s, wi_s);
    return __hfma2(hswap(v), wni, __hmul2(v, wrr));
}

__device__ __forceinline__ __half2 cmulh_t(__half2 v, uint2 u){
    return __hfma2(hswap(v), *(__half2*)&u.y, __hmul2(v, *(__half2*)&u.x));
}

template<bool INV>
__device__ __forceinline__ void dft16h(__half2 v[16]){
    const float S = INV ? 1.f : -1.f;
    bf4h<INV>(v[0], v[4], v[8],  v[12]);
    bf4h<INV>(v[1], v[5], v[9],  v[13]);
    bf4h<INV>(v[2], v[6], v[10], v[14]);
    bf4h<INV>(v[3], v[7], v[11], v[15]);
    v[5]  = cmulh_c(v[5],   0.92387953f, S*0.38268343f);
    v[9]  = cmulh_c(v[9],   0.70710678f, S*0.70710678f);
    v[13] = cmulh_c(v[13],  0.38268343f, S*0.92387953f);
    v[6]  = cmulh_c(v[6],   0.70710678f, S*0.70710678f);
    v[10] = mul_i_h<INV>(v[10]);
    v[14] = cmulh_c(v[14], -0.70710678f, S*0.70710678f);
    v[7]  = cmulh_c(v[7],   0.38268343f, S*0.92387953f);
    v[11] = cmulh_c(v[11], -0.70710678f, S*0.70710678f);
    v[15] = cmulh_c(v[15], -0.92387953f, -S*0.38268343f);
    bf4h<INV>(v[0],  v[1],  v[2],  v[3]);
    bf4h<INV>(v[4],  v[5],  v[6],  v[7]);
    bf4h<INV>(v[8],  v[9],  v[10], v[11]);
    bf4h<INV>(v[12], v[13], v[14], v[15]);
}

#define SLOT(k) ((((k) & 3) << 2) | ((k) >> 2))

__device__ __forceinline__ void build_twh(uint2* twf, uint2* twi, int tid){
    float s, c;
    __sincosf((float)tid * (-6.283185307179586f / 256.f), &s, &c);
    __half2 cc = __floats2half2_rn(c, c);
    __half2 nf = __floats2half2_rn(-s, s);
    __half2 ni = __floats2half2_rn(s, -s);
    uint2 u;
    u.x = *(unsigned int*)&cc;
    if (twf){ u.y = *(unsigned int*)&nf; twf[tid] = u; }
    if (twi){ u.y = *(unsigned int*)&ni; twi[tid] = u; }
}

// ---------------- MMA helpers ----------------
__device__ __forceinline__ unsigned s2u(const void* p){
    return (unsigned)__cvta_generic_to_shared(p);
}
__device__ __forceinline__ void ldmx4(unsigned* r, unsigned a){
    asm volatile("ldmatrix.sync.aligned.m8n8.x4.shared.b16 {%0,%1,%2,%3}, [%4];"
        : "=r"(r[0]), "=r"(r[1]), "=r"(r[2]), "=r"(r[3]) : "r"(a));
}
__device__ __forceinline__ void ldmx2t(unsigned& b0, unsigned& b1, unsigned a){
    asm volatile("ldmatrix.sync.aligned.m8n8.x2.trans.shared.b16 {%0,%1}, [%2];"
        : "=r"(b0), "=r"(b1) : "r"(a));
}
__device__ __forceinline__ void stmx2(unsigned a, unsigned r0, unsigned r1){
    asm volatile("stmatrix.sync.aligned.m8n8.x2.shared.b16 [%0], {%1,%2};"
        :: "r"(a), "r"(r0), "r"(r1) : "memory");
}
__device__ __forceinline__ void mma16816(float* c, const unsigned* a,
                                         unsigned b0, unsigned b1){
    asm volatile(
        "mma.sync.aligned.m16n8k16.row.col.f32.f16.f16.f32 "
        "{%0,%1,%2,%3}, {%4,%5,%6,%7}, {%8,%9}, {%0,%1,%2,%3};"
        : "+f"(c[0]), "+f"(c[1]), "+f"(c[2]), "+f"(c[3])
        : "r"(a[0]), "r"(a[1]), "r"(a[2]), "r"(a[3]), "r"(b0), "r"(b1));
}
__device__ __forceinline__ unsigned packh2(float a, float b){
    __half2 h = __floats2half2_rn(a, b);
    return *(unsigned*)&h;
}

// ---------------------------------------------------------------------------
// K1: row rfft, fp16 FFT. CTA = 32 rows, 2 real rows packed per complex FFT.
// Pair-fused epilogue: one Z1/Z2 load pair -> both packed rows -> one STG.64.
// ---------------------------------------------------------------------------
__global__ void __launch_bounds__(256) k_rowfft(const float* __restrict__ x){
    extern __shared__ char smraw[];
    __half2* bufh = (__half2*)smraw;               // 4352 h2  [0, 17408)
    uint2*   twf  = (uint2*)(smraw + 17408);       // 256 u2

    const int tid = threadIdx.x;
    const int f = tid >> 4, t = tid & 15;
    const int bc = blockIdx.x >> 3;
    const int h0 = (blockIdx.x & 7) << 5;

    build_twh(twf, nullptr, tid);

    const float* r0 = x + ((size_t)bc * HDIM + h0 + 2 * f) * WDIM;
    __half2 v[16];
#pragma unroll
    for (int n1 = 0; n1 < 16; n1++)
        v[n1] = __floats2half2_rn(r0[16 * n1 + t], r0[WDIM + 16 * n1 + t]);
    dft16h<false>(v);
    __syncthreads();                               // twf ready

#pragma unroll
    for (int k1 = 0; k1 < 16; k1++){
        __half2 bv = v[SLOT(k1)];
        if (k1) bv = cmulh_t(bv, twf[t * k1]);
        bufh[f * 272 + k1 * 17 + t] = bv;
    }
    __syncwarp();                                  // half-warp exchange only
#pragma unroll
    for (int n2 = 0; n2 < 16; n2++)
        v[n2] = bufh[f * 272 + t * 17 + n2];
    __syncthreads();                               // T dead -> S (cross-group)
    dft16h<false>(v);
#pragma unroll
    for (int k2 = 0; k2 < 16; k2++)
        bufh[f * 257 + t + 16 * k2] = v[SLOT(k2)];
    __syncthreads();

    __half2* dst = g_buf + (size_t)bc * WF * HDIM;
    for (int e = tid; e < WF * 16; e += 256){
        const int wf = e >> 4, fp = e & 15;
        float2 Z1 = __half22float2(bufh[fp * 257 + wf]);
        float2 Z2 = __half22float2(bufh[fp * 257 + ((256 - wf) & 255)]);
        __half2 o0 = __floats2half2_rn((Z1.x + Z2.x) * (1.f / 512.f),
                                       (Z1.y - Z2.y) * (1.f / 512.f));
        __half2 o1 = __floats2half2_rn((Z1.y + Z2.y) * (1.f / 512.f),
                                       (Z2.x - Z1.x) * (1.f / 512.f));
        uint2 st;
        st.x = *(unsigned*)&o0;
        st.y = *(unsigned*)&o1;
        *(uint2*)(dst + (size_t)wf * HDIM + h0 + 2 * fp) = st;
    }
}

// ---------------------------------------------------------------------------
// K2: packed-fp16 column FFT + HMMA block MLP + inverse FFT, in-place g_buf.
// Global column gather issued FIRST so its ~600cyc DRAM latency overlaps the
// twiddle/weight setup that follows.
// ---------------------------------------------------------------------------
__global__ void __launch_bounds__(256, 4) k_colfft_mlp(
        const float* __restrict__ w1g, const float* __restrict__ b1g,
        const float* __restrict__ w2g, const float* __restrict__ b2g){
    extern __shared__ char smraw[];
    __half*  Xs   = (__half*)smraw;                // 32 x 264   [0, 16896)
    __half2* Ts   = (__half2*)(smraw + 16896);     // transpose/Hs [16896, 34304)
    uint2*   twf  = (uint2*)(smraw + 34304);       // [34304, 36352)
    uint2*   twi  = (uint2*)(smraw + 36352);       // [36352, 38400)
    __half*  W1s  = (__half*)(smraw + 38400);      // 32 x 40    [38400, 40960)
    __half*  W2s  = (__half*)(smraw + 40960);      // 32 x 40    [40960, 43520)
    float*   b1s  = (float*)(smraw + 43520);       // 32         [43520, 43648)
    float*   b2s  = (float*)(smraw + 43648);       // 32         [43648, 43776)

    const int tid = threadIdx.x;
    const int f = tid >> 4, t = tid & 15;
    const int lane = tid & 31, wrp = tid >> 5;
    const int g = lane >> 2, tg = lane & 3;
    const int wf = blockIdx.x % WF;
    const int bk = blockIdx.x / WF;
    const int k = bk & 7, b = bk >> 3;

    // ---- issue the 16 column-gather LDGs FIRST (latency overlaps setup) ----
    __half2* chp = g_buf + ((size_t)(b * CSZ + k * 16 + f) * WF + wf) * HDIM;
    __half2 v[16];
#pragma unroll
    for (int n1 = 0; n1 < 16; n1++) v[n1] = chp[16 * n1 + t];

    build_twh(twf, twi, tid);
    {   // W_stack = [[Wr, -Wi],[Wi, Wr]]; w1/w2 are [2][8][16 in][16 out]
        const int i = tid >> 4, o = tid & 15;
        float wr = w1g[k * 256 + i * 16 + o], wi = w1g[2048 + k * 256 + i * 16 + o];
        W1s[o * 40 + i]             = __float2half(wr);
        W1s[o * 40 + 16 + i]        = __float2half(-wi);
        W1s[(16 + o) * 40 + i]      = __float2half(wi);
        W1s[(16 + o) * 40 + 16 + i] = __float2half(wr);
        wr = w2g[k * 256 + i * 16 + o]; wi = w2g[2048 + k * 256 + i * 16 + o];
        W2s[o * 40 + i]             = __float2half(wr);
        W2s[o * 40 + 16 + i]        = __float2half(-wi);
        W2s[(16 + o) * 40 + i]      = __float2half(wi);
        W2s[(16 + o) * 40 + 16 + i] = __float2half(wr);
    }
    if (tid < 16){
        b1s[tid] = b1g[k * 16 + tid];  b1s[16 + tid] = b1g[128 + k * 16 + tid];
        b2s[tid] = b2g[k * 16 + tid];  b2s[16 + tid] = b2g[128 + k * 16 + tid];
    }

    // ---- forward column FFT ----
    dft16h<false>(v);
    __syncthreads();                               // tables + weights ready
#pragma unroll
    for (int k1 = 0; k1 < 16; k1++){
        __half2 bv = v[SLOT(k1)];
        if (k1) bv = cmulh_t(bv, twf[t * k1]);
        Ts[f * 272 + k1 * 17 + t] = bv;            // T write
    }
    __syncwarp();                                  // half-warp exchange
#pragma unroll
    for (int n2 = 0; n2 < 16; n2++) v[n2] = Ts[f * 272 + t * 17 + n2];  // T read
    dft16h<false>(v);
#pragma unroll
    for (int k2 = 0; k2 < 16; k2++){               // X stacked-row write
        const int bin = t + (k2 << 4);
        __half2 z = v[SLOT(k2)];
        Xs[f * 264 + bin]        = __low2half(z);
        Xs[(16 + f) * 264 + bin] = __high2half(z);
    }
    __syncthreads();                               // X ready; Ts free -> Hs

    // ---- MLP via HMMA: each warp owns 32 columns ----
    {
        const unsigned rowsel = lane & 15;
        const unsigned XsB = s2u(Xs), HsB = s2u((__half*)Ts);
        float b1v0 = b1s[g], b1v1 = b1s[g + 8], b1v2 = b1s[16 + g], b1v3 = b1s[24 + g];

        unsigned A1[4][4];
#pragma unroll
        for (int m = 0; m < 2; m++)
#pragma unroll
            for (int kt = 0; kt < 2; kt++)
                ldmx4(A1[m * 2 + kt],
                      s2u(W1s) + (((m * 16 + rowsel) * 40 + kt * 16 + (lane >> 4) * 8) << 1));

#pragma unroll
        for (int nt = 0; nt < 4; nt++){
            const int n0 = wrp * 32 + nt * 8;
            unsigned bx0, bx1, by0, by1;
            ldmx2t(bx0, bx1, XsB + ((rowsel * 264 + n0) << 1));
            ldmx2t(by0, by1, XsB + (((16 + rowsel) * 264 + n0) << 1));
            float cr[4] = {0.f, 0.f, 0.f, 0.f}, ci[4] = {0.f, 0.f, 0.f, 0.f};
            mma16816(cr, A1[0], bx0, bx1);
            mma16816(cr, A1[1], by0, by1);
            mma16816(ci, A1[2], bx0, bx1);
            mma16816(ci, A1[3], by0, by1);
            unsigned hr0 = packh2(fmaxf(cr[0] + b1v0, 0.f), fmaxf(cr[1] + b1v0, 0.f));
            unsigned hr1 = packh2(fmaxf(cr[2] + b1v1, 0.f), fmaxf(cr[3] + b1v1, 0.f));
            unsigned hi0 = packh2(fmaxf(ci[0] + b1v2, 0.f), fmaxf(ci[1] + b1v2, 0.f));
            unsigned hi1 = packh2(fmaxf(ci[2] + b1v3, 0.f), fmaxf(ci[3] + b1v3, 0.f));
            stmx2(HsB + ((rowsel * 264 + n0) << 1), hr0, hr1);
            stmx2(HsB + (((16 + rowsel) * 264 + n0) << 1), hi0, hi1);
        }
        __syncwarp();

        unsigned A2[4][4];
#pragma unroll
        for (int m = 0; m < 2; m++)
#pragma unroll
            for (int kt = 0; kt < 2; kt++)
                ldmx4(A2[m * 2 + kt],
                      s2u(W2s) + (((m * 16 + rowsel) * 40 + kt * 16 + (lane >> 4) * 8) << 1));
        float b2v0 = b2s[g], b2v1 = b2s[g + 8], b2v2 = b2s[16 + g], b2v3 = b2s[24 + g];

#pragma unroll
        for (int nt = 0; nt < 4; nt++){
            const int n0 = wrp * 32 + nt * 8;
            unsigned bx0, bx1, by0, by1;
            ldmx2t(bx0, bx1, HsB + ((rowsel * 264 + n0) << 1));
            ldmx2t(by0, by1, HsB + (((16 + rowsel) * 264 + n0) << 1));
            float cr[4] = {0.f, 0.f, 0.f, 0.f}, ci[4] = {0.f, 0.f, 0.f, 0.f};
            mma16816(cr, A2[0], bx0, bx1);
            mma16816(cr, A2[1], by0, by1);
            mma16816(ci, A2[2], bx0, bx1);
            mma16816(ci, A2[3], by0, by1);
#pragma unroll
            for (int j = 0; j < 4; j++){
                const int o = g + ((j >> 1) << 3);
                const int bin = n0 + 2 * tg + (j & 1);
                const float yr = cr[j] + ((j >> 1) ? b2v1 : b2v0);
                const float yi = ci[j] + ((j >> 1) ? b2v3 : b2v2);
                const float sr = copysignf(fmaxf(fabsf(yr) - 0.01f, 0.f), yr);
                const float si = copysignf(fmaxf(fabsf(yi) - 0.01f, 0.f), yi);
                const float xr = __half2float(Xs[o * 264 + bin]);
                const float xi = __half2float(Xs[(o + 16) * 264 + bin]);
                Xs[o * 264 + bin]        = __float2half(sr * xr - si * xi);
                Xs[(o + 16) * 264 + bin] = __float2half(sr * xi + si * xr);
            }
        }
    }
    __syncthreads();                               // result in Xs; Hs reads done

    // ---- inverse column FFT (A from Xs stacked rows, transpose via Ts) ----
#pragma unroll
    for (int k2 = 0; k2 < 16; k2++){
        const int bin = t + (k2 << 4);
        v[k2] = __halves2half2(Xs[f * 264 + bin], Xs[(16 + f) * 264 + bin]);
    }
    dft16h<true>(v);
#pragma unroll
    for (int m2 = 0; m2 < 16; m2++){
        __half2 q = v[SLOT(m2)];
        if (m2) q = cmulh_t(q, twi[m2 * t]);
        Ts[f * 272 + m2 * 17 + t] = q;             // T write
    }
    __syncwarp();
#pragma unroll
    for (int n = 0; n < 16; n++) v[n] = Ts[f * 272 + t * 17 + n];       // T read
    dft16h<true>(v);
#pragma unroll
    for (int m1 = 0; m1 < 16; m1++)
        chp[16 * m1 + t] = v[SLOT(m1)];
}

// ---------------------------------------------------------------------------
// K3: row irfft, fp16 FFT. Hermitian extension + edge-bin imag zeroing ==
// irfft semantics. Scale 1/256 + residual in fp32.
// ---------------------------------------------------------------------------
__global__ void __launch_bounds__(256) k_rowifft(const float* __restrict__ x,
                                                 float* __restrict__ out){
    extern __shared__ char smraw[];
    __half2* bufh = (__half2*)smraw;               // 4352 h2
    uint2*   twi  = (uint2*)(smraw + 17408);       // 256 u2

    const int tid = threadIdx.x;
    const int f = tid >> 4, t = tid & 15;
    const int bc = blockIdx.x >> 3;
    const int h0 = (blockIdx.x & 7) << 5;

    build_twh(nullptr, twi, tid);

    const __half2* gsrc = g_buf + (size_t)bc * WF * HDIM;
    for (int e = tid; e < WF * 16; e += 256){
        const int wf = e >> 4, fp = e & 15;
        uint2 u = *(const uint2*)(gsrc + (size_t)wf * HDIM + h0 + 2 * fp);
        float2 a  = __half22float2(*(__half2*)&u.x);
        float2 bq = __half22float2(*(__half2*)&u.y);
        float ay = a.y, by = bq.y;
        if (wf == 0 || wf == 128){ ay = 0.f; by = 0.f; }
        bufh[fp * 257 + wf] = __floats2half2_rn(a.x - by, ay + bq.x);
        if (wf >= 1 && wf <= 127)
            bufh[fp * 257 + 256 - wf] = __floats2half2_rn(a.x + by, bq.x - ay);
    }
    __syncthreads();

    __half2 v[16];
#pragma unroll
    for (int k2 = 0; k2 < 16; k2++) v[k2] = bufh[f * 257 + t + 16 * k2];
    __syncthreads();                               // S dead -> T (cross-group)
    dft16h<true>(v);
#pragma unroll
    for (int m2 = 0; m2 < 16; m2++){
        __half2 q = v[SLOT(m2)];
        if (m2) q = cmulh_t(q, twi[m2 * t]);
        bufh[f * 272 + m2 * 17 + t] = q;
    }
    __syncwarp();                                  // half-warp exchange only
#pragma unroll
    for (int n = 0; n < 16; n++) v[n] = bufh[f * 272 + t * 17 + n];
    dft16h<true>(v);

    const float* bias0 = x   + ((size_t)bc * HDIM + h0 + 2 * f) * WDIM;
    float*       o0    = out + ((size_t)bc * HDIM + h0 + 2 * f) * WDIM;
#pragma unroll
    for (int m1 = 0; m1 < 16; m1++){
        float2 z = __half22float2(v[SLOT(m1)]);
        const int w_ = 16 * m1 + t;
        o0[w_]        = z.x * (1.f / 256.f) + bias0[w_];
        o0[WDIM + w_] = z.y * (1.f / 256.f) + bias0[WDIM + w_];
    }
}

extern "C" void kernel_launch(void* const* d_in, const int* in_sizes, int n_in,
                              void* d_out, int out_size) {
    const float* x  = (const float*)d_in[0];
    const float* w1 = (const float*)d_in[1];
    const float* b1 = (const float*)d_in[2];
    const float* w2 = (const float*)d_in[3];
    const float* b2 = (const float*)d_in[4];
    float* out = (float*)d_out;

    const int SMEM_ROW = 19456;
    const int SMEM_COL = 43776;

    cudaFuncSetAttribute(k_rowfft,     cudaFuncAttributeMaxDynamicSharedMemorySize, SMEM_ROW);
    cudaFuncSetAttribute(k_colfft_mlp, cudaFuncAttributeMaxDynamicSharedMemorySize, SMEM_COL);
    cudaFuncSetAttribute(k_rowifft,    cudaFuncAttributeMaxDynamicSharedMemorySize, SMEM_ROW);

    k_rowfft<<<BSZ * CSZ * (HDIM / 32), 256, SMEM_ROW>>>(x);
    k_colfft_mlp<<<BSZ * NBLK * WF, 256, SMEM_COL>>>(w1, b1, w2, b2);
    k_rowifft<<<BSZ * CSZ * (HDIM / 32), 256, SMEM_ROW>>>(x, out);
}